// round 10
// baseline (speedup 1.0000x reference)
#include <cuda_runtime.h>
#include <stdint.h>

// dice_shape_loss: mean over 64*1*448*448 = 12,845,056 elements of
//   a = -(y*max(log p,-100) + (1-y)*max(log(1-p),-100));  out = mean(a*(1+shapeloss))
// HBM-bound streaming reduction: 154.1 MB read, 4 B write, ~5.9 TB/s pattern ceiling.
// R10 (= R9 resubmit; R9 died to broker flake): R7's two-log body (measured
// 27.0us kernel; its register pressure keeps the prefetch loads front-batched
// -> 71.6% DRAM) + R8's single-kernel last-block finalize (measured 0.61us
// node overhead vs 1.69us for the two-node graph).

#define LOG_CLAMP (-100.0f)

#define NBLOCKS  (148 * 6)
#define NTHREADS 256

__device__ float        g_partials[NBLOCKS];
__device__ unsigned int g_count = 0;   // self-resetting ticket (0 after every call)

__device__ __forceinline__ float elem_loss(float t, float p, float s) {
    float lp = fmaxf(__logf(p), LOG_CLAMP);
    float lq = fmaxf(__logf(1.0f - p), LOG_CLAMP);
    // a = -(t*lp + (1-t)*lq)   (t is exactly 0.0 or 1.0)
    float a = -fmaf(t, lp - lq, lq);
    return fmaf(a, s, a);   // a*s + a
}

__device__ __forceinline__ float quad_loss(float4 t, float4 p, float4 s) {
    float acc;
    acc  = elem_loss(t.x, p.x, s.x);
    acc += elem_loss(t.y, p.y, s.y);
    acc += elem_loss(t.z, p.z, s.z);
    acc += elem_loss(t.w, p.w, s.w);
    return acc;
}

__global__ void __launch_bounds__(NTHREADS)
bce_shape_reduce_kernel(const float4* __restrict__ yt,
                        const float4* __restrict__ yp,
                        const float4* __restrict__ sl,
                        float* __restrict__ out,
                        int n4, float inv_n) {
    float acc = 0.0f;
    int idx    = blockIdx.x * blockDim.x + threadIdx.x;
    int stride = gridDim.x * blockDim.x;

    // Software-pipelined grid-stride loop (R7 body, measured 27.0us / 71.6% DRAM).
    if (idx < n4) {
        float4 t0 = __ldcs(yt + idx);
        float4 p0 = __ldcs(yp + idx);
        float4 s0 = __ldcs(sl + idx);
        for (int j = idx + stride; j < n4; j += stride) {
            float4 t1 = __ldcs(yt + j);
            float4 p1 = __ldcs(yp + j);
            float4 s1 = __ldcs(sl + j);
            acc += quad_loss(t0, p0, s0);
            t0 = t1; p0 = p1; s0 = s1;
        }
        acc += quad_loss(t0, p0, s0);
    }

    // intra-block reduction
    #pragma unroll
    for (int o = 16; o > 0; o >>= 1)
        acc += __shfl_down_sync(0xFFFFFFFFu, acc, o);

    __shared__ float warp_sums[NTHREADS / 32];
    __shared__ bool  s_is_last;
    int lane = threadIdx.x & 31;
    int wid  = threadIdx.x >> 5;
    if (lane == 0) warp_sums[wid] = acc;
    __syncthreads();

    if (wid == 0) {
        float v = (lane < (NTHREADS / 32)) ? warp_sums[lane] : 0.0f;
        #pragma unroll
        for (int o = 4; o > 0; o >>= 1)
            v += __shfl_down_sync(0xFFFFFFFFu, v, o);
        if (lane == 0) {
            g_partials[blockIdx.x] = v;
            __threadfence();                        // partial visible before ticket
            unsigned int prev = atomicAdd(&g_count, 1u);
            s_is_last = (prev == (unsigned int)(NBLOCKS - 1));
        }
    }
    __syncthreads();   // publish s_is_last to the whole block

    // Last block to arrive reduces all partials and writes the scalar output.
    float v = 0.0f;
    if (s_is_last) {
        __threadfence();                            // order partial reads after ticket
        for (int j = threadIdx.x; j < NBLOCKS; j += NTHREADS)
            v += g_partials[j];
        #pragma unroll
        for (int o = 16; o > 0; o >>= 1)
            v += __shfl_down_sync(0xFFFFFFFFu, v, o);
        if (lane == 0) warp_sums[wid] = v;
    }
    __syncthreads();
    if (s_is_last && wid == 0) {
        float w = (lane < (NTHREADS / 32)) ? warp_sums[lane] : 0.0f;
        #pragma unroll
        for (int o = 4; o > 0; o >>= 1)
            w += __shfl_down_sync(0xFFFFFFFFu, w, o);
        if (lane == 0) {
            out[0] = w * inv_n;
            __threadfence();
            g_count = 0;   // reset ticket: deterministic across graph replays
        }
    }
}

extern "C" void kernel_launch(void* const* d_in, const int* in_sizes, int n_in,
                              void* d_out, int out_size) {
    const float4* yt = (const float4*)d_in[0];  // y_true
    const float4* yp = (const float4*)d_in[1];  // y_pred
    const float4* sl = (const float4*)d_in[2];  // shapeloss
    float* out = (float*)d_out;

    int n  = in_sizes[0];            // 12,845,056
    int n4 = n >> 2;                 // 3,211,264
    float inv_n = 1.0f / (float)n;

    bce_shape_reduce_kernel<<<NBLOCKS, NTHREADS>>>(yt, yp, sl, out, n4, inv_n);
}

// round 12
// speedup vs baseline: 1.0853x; 1.0853x over previous
#include <cuda_runtime.h>
#include <stdint.h>

// dice_shape_loss: mean over 64*1*448*448 = 12,845,056 elements of
//   a = -(y*max(log p,-100) + (1-y)*max(log(1-p),-100));  out = mean(a*(1+shapeloss))
// HBM/LTS-bound streaming reduction: 154.1 MB read, 4 B write, ~5.9 TB/s ceiling.
// R12 (= R11 resubmit; R11 died to broker flake): R7's proven two-node
// structure (28.70us, reproduced twice) with the zero-kernel node overlapped
// via PDL (programmatic dependent launch). Main kernel streams immediately;
// griddepcontrol.wait gates only the final atomicAdd on the zero-kernel's
// completion. Falls back to exact R7 behavior if PDL is serialized.

#define LOG_CLAMP (-100.0f)

#define NBLOCKS  (148 * 6)
#define NTHREADS 256

__global__ void zero_out_kernel(float* out) {
    if (threadIdx.x == 0) out[0] = 0.0f;
    // Signal dependents may flush their waits as soon as the store is done.
    asm volatile("griddepcontrol.launch_dependents;" ::: "memory");
}

__device__ __forceinline__ float elem_loss(float t, float p, float s) {
    float lp = fmaxf(__logf(p), LOG_CLAMP);
    float lq = fmaxf(__logf(1.0f - p), LOG_CLAMP);
    // a = -(t*lp + (1-t)*lq)   (t is exactly 0.0 or 1.0)
    float a = -fmaf(t, lp - lq, lq);
    return fmaf(a, s, a);   // a*s + a
}

__device__ __forceinline__ float quad_loss(float4 t, float4 p, float4 s) {
    float acc;
    acc  = elem_loss(t.x, p.x, s.x);
    acc += elem_loss(t.y, p.y, s.y);
    acc += elem_loss(t.z, p.z, s.z);
    acc += elem_loss(t.w, p.w, s.w);
    return acc;
}

__global__ void __launch_bounds__(NTHREADS)
bce_shape_reduce_kernel(const float4* __restrict__ yt,
                        const float4* __restrict__ yp,
                        const float4* __restrict__ sl,
                        float* __restrict__ out,
                        int n4, float inv_n) {
    float acc = 0.0f;
    int idx    = blockIdx.x * blockDim.x + threadIdx.x;
    int stride = gridDim.x * blockDim.x;

    // Software-pipelined grid-stride loop (R7 body, measured 27.0us / 71.6% DRAM).
    // Does NOT touch `out`, so it runs concurrently with zero_out_kernel under PDL.
    if (idx < n4) {
        float4 t0 = __ldcs(yt + idx);
        float4 p0 = __ldcs(yp + idx);
        float4 s0 = __ldcs(sl + idx);
        for (int j = idx + stride; j < n4; j += stride) {
            float4 t1 = __ldcs(yt + j);
            float4 p1 = __ldcs(yp + j);
            float4 s1 = __ldcs(sl + j);
            acc += quad_loss(t0, p0, s0);
            t0 = t1; p0 = p1; s0 = s1;
        }
        acc += quad_loss(t0, p0, s0);
    }

    // intra-block reduction
    #pragma unroll
    for (int o = 16; o > 0; o >>= 1)
        acc += __shfl_down_sync(0xFFFFFFFFu, acc, o);

    __shared__ float warp_sums[NTHREADS / 32];
    int lane = threadIdx.x & 31;
    int wid  = threadIdx.x >> 5;
    if (lane == 0) warp_sums[wid] = acc;
    __syncthreads();

    if (wid == 0) {
        float v = (lane < (NTHREADS / 32)) ? warp_sums[lane] : 0.0f;
        #pragma unroll
        for (int o = 4; o > 0; o >>= 1)
            v += __shfl_down_sync(0xFFFFFFFFu, v, o);
        // Gate ONLY the out-access on the predecessor kernel's completion.
        asm volatile("griddepcontrol.wait;" ::: "memory");
        if (lane == 0)
            atomicAdd(out, v * inv_n);
    }
}

extern "C" void kernel_launch(void* const* d_in, const int* in_sizes, int n_in,
                              void* d_out, int out_size) {
    const float4* yt = (const float4*)d_in[0];  // y_true
    const float4* yp = (const float4*)d_in[1];  // y_pred
    const float4* sl = (const float4*)d_in[2];  // shapeloss
    float* out = (float*)d_out;

    int n  = in_sizes[0];            // 12,845,056
    int n4 = n >> 2;                 // 3,211,264
    float inv_n = 1.0f / (float)n;

    zero_out_kernel<<<1, 32>>>(out);

    // Launch the main kernel with programmatic dependent launch so its blocks
    // start while zero_out_kernel is still in flight; the griddepcontrol.wait
    // inside orders only the atomicAdd after the zeroing.
    cudaLaunchConfig_t cfg = {};
    cfg.gridDim        = dim3(NBLOCKS);
    cfg.blockDim       = dim3(NTHREADS);
    cfg.dynamicSmemBytes = 0;
    cfg.stream         = 0;   // same (captured) stream as the <<<>>> launch above
    cudaLaunchAttribute attr[1];
    attr[0].id = cudaLaunchAttributeProgrammaticStreamSerialization;
    attr[0].val.programmaticStreamSerializationAllowed = 1;
    cfg.attrs    = attr;
    cfg.numAttrs = 1;

    cudaLaunchKernelEx(&cfg, bce_shape_reduce_kernel, yt, yp, sl, out, n4, inv_n);
}